// round 11
// baseline (speedup 1.0000x reference)
#include <cuda_runtime.h>
#include <cuda_fp16.h>
#include <cstdint>

// ---------------- problem constants ----------------
#define KB      8
#define DIM     64
#define CB      1024
#define ROWS    8192
#define D_FULL  512
#define MT      128              // rows per CTA
#define NMT     (ROWS/MT)        // 64
#define NTHR    256
#define NCHUNK  8                // code chunks of 128
#define NCTAS   (NMT*KB)         // 512

#define CODES_ELEMS (ROWS*KB*DIM)            // 4194304
#define INDS_OFF    CODES_ELEMS
#define COMMIT_OFF  (CODES_ELEMS + ROWS*KB)  // 4259840

// ---------------- device scratch ----------------
__device__ float  g_esq[KB*CB];
__device__ float  g_part[KB*NMT];
__device__ __half g_Bh[(size_t)KB*CB*DIM];   // 1 MB
__device__ int    g_ctr;                     // zero-initialized; reset by last CTA

// ---------------- smem layout (bytes, dynamic) ----------------
#define SM_ESQ    0                 // 4096
#define SM_AH     4096              // 16384
#define SM_B      20480             // 3 stages x 16384 = 49152
#define SM_MB1    69632             // 2*128 floats
#define SM_MB2    70656             // 2*128 floats
#define SM_RED    71680             // 256 floats
#define SM_TOTAL  72704

#define SWZ(bo) ((bo) ^ (((bo) >> 3) & 0x70))

// ---------------- helpers ----------------
__device__ __forceinline__ uint32_t smem_u32(const void* p) {
    uint32_t a;
    asm("{ .reg .u64 t; cvta.to.shared.u64 t, %1; cvt.u32.u64 %0, t; }" : "=r"(a) : "l"(p));
    return a;
}
__device__ __forceinline__ void cp16(uint32_t saddr, const void* gptr) {
    asm volatile("cp.async.cg.shared.global [%0], [%1], 16;"
                 :: "r"(saddr), "l"(gptr) : "memory");
}
#define CP_COMMIT() asm volatile("cp.async.commit_group;" ::: "memory")
#define CP_WAIT(n)  asm volatile("cp.async.wait_group %0;" :: "n"(n) : "memory")

__device__ __forceinline__ void ldsm_x4(uint32_t& r0, uint32_t& r1,
                                        uint32_t& r2, uint32_t& r3, uint32_t addr) {
    asm volatile("ldmatrix.sync.aligned.m8n8.x4.shared.b16 {%0,%1,%2,%3}, [%4];"
                 : "=r"(r0), "=r"(r1), "=r"(r2), "=r"(r3) : "r"(addr));
}
__device__ __forceinline__ void mma16816(float* c, const uint32_t* a, const uint32_t* b) {
    asm volatile("mma.sync.aligned.m16n8k16.row.col.f32.f16.f16.f32 "
                 "{%0,%1,%2,%3}, {%4,%5,%6,%7}, {%8,%9}, {%0,%1,%2,%3};"
                 : "+f"(c[0]), "+f"(c[1]), "+f"(c[2]), "+f"(c[3])
                 : "r"(a[0]), "r"(a[1]), "r"(a[2]), "r"(a[3]), "r"(b[0]), "r"(b[1]));
}
__device__ __forceinline__ uint32_t pack_h2(float a, float b) {
    __half2 h = __floats2half2_rn(a, b);
    return *reinterpret_cast<uint32_t*>(&h);
}
// pack score with 10-bit code index in low mantissa bits (branchless argmin key)
__device__ __forceinline__ float pk(float v, int code) {
    return __uint_as_float((__float_as_uint(v) & 0xFFFFFC00u) | (uint32_t)code);
}
// branchless 2-smallest insert
__device__ __forceinline__ void min2(float& B1, float& B2, float v) {
    float lo = fminf(B1, v);
    float hi = fmaxf(B1, v);
    B1 = lo;
    B2 = fminf(B2, hi);
}
// merge two sorted pairs -> 2 smallest of 4 (branchless)
__device__ __forceinline__ void merge2(float& B1, float& B2, float o1, float o2) {
    float lo = fminf(B1, o1);
    float hi = fmaxf(B1, o1);
    B2 = fminf(fminf(B2, o2), hi);
    B1 = lo;
}

// ---------------- kernel: esq + codebook fp16 split (4 threads/code) ------------
__global__ void prep_cb_kernel(const float* __restrict__ cb) {
    int idx = blockIdx.x * blockDim.x + threadIdx.x;   // 0..32767
    int c = idx >> 2, h = idx & 3;
    const float4* p = reinterpret_cast<const float4*>(cb + (size_t)c * DIM + h * 16);
    uint2* ph = reinterpret_cast<uint2*>(g_Bh + (size_t)c * DIM + h * 16);
    float s = 0.f;
#pragma unroll
    for (int i = 0; i < 4; i++) {
        float4 v = p[i];
        s += v.x * v.x + v.y * v.y + v.z * v.z + v.w * v.w;
        uint2 uh;
        uh.x = pack_h2(v.x, v.y);
        uh.y = pack_h2(v.z, v.w);
        ph[i] = uh;
    }
    s += __shfl_xor_sync(0xffffffffu, s, 1);
    s += __shfl_xor_sync(0xffffffffu, s, 2);
    if (h == 0) g_esq[c] = s;
}

// ---------------- main kernel: cp.async 3-stage fp16 1-pass + packed argmin ------
__global__ __launch_bounds__(NTHR, 2)
void vq_mma_kernel(const float* __restrict__ x,
                   const float* __restrict__ cbook,
                   float* __restrict__ out) {
    extern __shared__ char smem[];
    const uint32_t sb = smem_u32(smem);
    float* esq_s = reinterpret_cast<float*>(smem + SM_ESQ);

    const int t = threadIdx.x, wid = t >> 5, l = t & 31;
    const int mtb = blockIdx.x, kb = blockIdx.y;
    const int warp_r = wid & 3;          // 4 row groups of 32 rows
    const int warp_c = wid >> 2;         // 2 code halves of 64 codes

    // ---- prefetch chunk 0 (B hi) via cp.async ----
    {
        const char* gh = reinterpret_cast<const char*>(g_Bh + (size_t)kb * CB * DIM);
#pragma unroll
        for (int i = 0; i < 4; i++) {
            int f = t + i * NTHR;
            uint32_t bo = SWZ((uint32_t)f * 16u);
            cp16(sb + SM_B + bo, gh + (size_t)f * 16);
        }
        CP_COMMIT();
    }

    // stage esq (exact fp32)
    for (int i = t; i < CB; i += NTHR) esq_s[i] = g_esq[kb * CB + i];

    // ---- stage A: x tile as fp16, swizzled ----
    {
        const int r = t >> 1, h = t & 1;
        const float4* src = reinterpret_cast<const float4*>(
            x + (size_t)(mtb * MT + r) * D_FULL + kb * DIM + h * 32);
#pragma unroll
        for (int j = 0; j < 8; j++) {
            float4 v = src[j];
            uint2 uh;
            uh.x = pack_h2(v.x, v.y);
            uh.y = pack_h2(v.z, v.w);
            uint32_t bo = SWZ((uint32_t)(r * 128 + h * 64 + j * 8));
            *reinterpret_cast<uint2*>(smem + SM_AH + bo) = uh;
        }
    }

    float best1[4], best2[4];
#pragma unroll
    for (int s = 0; s < 4; s++) { best1[s] = 3.4e38f; best2[s] = 3.4e38f; }

    // stage index ring (mod 3)
    int cur = 0, nxt = 1;
#pragma unroll 1
    for (int ch = 0; ch < NCHUNK; ch++) {
        const uint32_t stg = sb + SM_B + (uint32_t)cur * 16384u;
        // issue prefetch of chunk ch+1 into the next ring stage, then wait for ch
        if (ch < NCHUNK - 1) {
            const uint32_t nstg = sb + SM_B + (uint32_t)nxt * 16384u;
            const char* gh = reinterpret_cast<const char*>(
                g_Bh + ((size_t)kb * CB + (ch + 1) * 128) * DIM);
#pragma unroll
            for (int i = 0; i < 4; i++) {
                int f = t + i * NTHR;
                uint32_t bo = SWZ((uint32_t)f * 16u);
                cp16(nstg + bo, gh + (size_t)f * 16);
            }
            CP_COMMIT();
            CP_WAIT(1);
        } else {
            CP_WAIT(0);
        }
        __syncthreads();   // single barrier/iter: bounds warp skew < 1 iter;
                           // with 3 stages the write target never collides

#pragma unroll 1
        for (int nh = 0; nh < 2; nh++) {              // 2 halves of 32 codes
            float acc[2][4][4];
#pragma unroll
            for (int m = 0; m < 2; m++)
#pragma unroll
                for (int n = 0; n < 4; n++)
#pragma unroll
                    for (int q = 0; q < 4; q++) acc[m][n][q] = 0.f;

            // single pass: xh * eh (residuals handled by exact top-2 rescore)
#pragma unroll
            for (int ks = 0; ks < 4; ks++) {
                uint32_t a[2][4];
#pragma unroll
                for (int m = 0; m < 2; m++) {
                    int row = warp_r * 32 + m * 16 + (l & 15);
                    uint32_t ad = sb + SM_AH +
                        SWZ((uint32_t)(row * 128 + ks * 32 + (l >> 4) * 16));
                    ldsm_x4(a[m][0], a[m][1], a[m][2], a[m][3], ad);
                }
                uint32_t b[4][2];
#pragma unroll
                for (int np = 0; np < 2; np++) {
                    int crow = warp_c * 64 + nh * 32 + np * 16 +
                               ((l >> 4) & 1) * 8 + (l & 7);
                    uint32_t bd = stg +
                        SWZ((uint32_t)(crow * 128 + ks * 32 + ((l >> 3) & 1) * 16));
                    uint32_t r0, r1, r2, r3;
                    ldsm_x4(r0, r1, r2, r3, bd);
                    b[np * 2][0] = r0;     b[np * 2][1] = r1;
                    b[np * 2 + 1][0] = r2; b[np * 2 + 1][1] = r3;
                }
#pragma unroll
                for (int m = 0; m < 2; m++)
#pragma unroll
                    for (int n = 0; n < 4; n++)
                        mma16816(acc[m][n], a[m], b[n]);
            }

            // ---- scoring: packed (score|code), branchless 2-min network ----
#pragma unroll
            for (int m = 0; m < 2; m++)
#pragma unroll
                for (int n = 0; n < 4; n++) {
                    int cbase = ch * 128 + warp_c * 64 + nh * 32 + n * 8 + 2 * (l & 3);
                    float e0 = esq_s[cbase], e1 = esq_s[cbase + 1];
                    const int s0 = 2 * m, s1 = 2 * m + 1;
                    min2(best1[s0], best2[s0], pk(fmaf(-2.f, acc[m][n][0], e0), cbase));
                    min2(best1[s0], best2[s0], pk(fmaf(-2.f, acc[m][n][1], e1), cbase + 1));
                    min2(best1[s1], best2[s1], pk(fmaf(-2.f, acc[m][n][2], e0), cbase));
                    min2(best1[s1], best2[s1], pk(fmaf(-2.f, acc[m][n][3], e1), cbase + 1));
                }
        }
        cur = nxt;
        nxt = (nxt == 2) ? 0 : nxt + 1;
    }

    // ---- reduce top-2 across the 4 lanes of each quad (l&3) ----
#pragma unroll
    for (int s = 0; s < 4; s++) {
#pragma unroll
        for (int m = 1; m <= 2; m <<= 1) {
            float o1 = __shfl_xor_sync(0xffffffffu, best1[s], m);
            float o2 = __shfl_xor_sync(0xffffffffu, best2[s], m);
            merge2(best1[s], best2[s], o1, o2);
        }
    }
    __syncthreads();
    float* mb1 = reinterpret_cast<float*>(smem + SM_MB1);
    float* mb2 = reinterpret_cast<float*>(smem + SM_MB2);
    if ((l & 3) == 0) {
#pragma unroll
        for (int s = 0; s < 4; s++) {
            int row = warp_r * 32 + (s >> 1) * 16 + (s & 1) * 8 + (l >> 2);
            mb1[warp_c * 128 + row] = best1[s];
            mb2[warp_c * 128 + row] = best2[s];
        }
    }
    __syncthreads();

    // ---- per-row epilogue (threads 0..127) ----
    float csum = 0.f;
    if (t < MT) {
        float B1 = mb1[t], B2 = mb2[t];
        merge2(B1, B2, mb1[128 + t], mb2[128 + t]);
        int I1 = (int)(__float_as_uint(B1) & 1023u);
        int I2 = (int)(__float_as_uint(B2) & 1023u);

        const int row_g = mtb * MT + t;
        const float4* xp = reinterpret_cast<const float4*>(
            x + (size_t)row_g * D_FULL + kb * DIM);
        float4 xr[16];
#pragma unroll
        for (int i = 0; i < 16; i++) xr[i] = xp[i];

        // near-tie safety: exact fp32 rescore of top-2
        // (fp16 approx err ~5.4e-3 + packing noise ~0.03 << 0.15 threshold)
        if (B2 - B1 < 0.15f) {
            const float* base = cbook + (size_t)kb * CB * DIM;
            float d1 = 0.f, d2 = 0.f;
            const float4* p1 = reinterpret_cast<const float4*>(base + (size_t)I1 * DIM);
            const float4* p2 = reinterpret_cast<const float4*>(base + (size_t)I2 * DIM);
#pragma unroll
            for (int i = 0; i < 16; i++) {
                float4 e1 = p1[i], e2 = p2[i];
                d1 = fmaf(xr[i].x, e1.x, d1); d1 = fmaf(xr[i].y, e1.y, d1);
                d1 = fmaf(xr[i].z, e1.z, d1); d1 = fmaf(xr[i].w, e1.w, d1);
                d2 = fmaf(xr[i].x, e2.x, d2); d2 = fmaf(xr[i].y, e2.y, d2);
                d2 = fmaf(xr[i].z, e2.z, d2); d2 = fmaf(xr[i].w, e2.w, d2);
            }
            float s1 = fmaf(-2.f, d1, esq_s[I1]);
            float s2 = fmaf(-2.f, d2, esq_s[I2]);
            if (s2 < s1 || (s2 == s1 && I2 < I1)) I1 = I2;
        }

        out[INDS_OFF + (size_t)row_g * KB + kb] = (float)I1;

        const float4* ep = reinterpret_cast<const float4*>(
            cbook + ((size_t)kb * CB + I1) * DIM);
        float4* op = reinterpret_cast<float4*>(
            out + (size_t)row_g * D_FULL + kb * DIM);
#pragma unroll
        for (int i = 0; i < 16; i++) {
            float4 e = ep[i];
            op[i] = e;
            float dx = xr[i].x - e.x, dy = xr[i].y - e.y;
            float dz = xr[i].z - e.z, dw = xr[i].w - e.w;
            csum += dx * dx + dy * dy + dz * dz + dw * dw;
        }
    }

    // deterministic commit-partial block reduce
    float* s_red = reinterpret_cast<float*>(smem + SM_RED);
    s_red[t] = csum;
    __syncthreads();
    for (int s = NTHR / 2; s > 0; s >>= 1) {
        if (t < s) s_red[t] += s_red[t + s];
        __syncthreads();
    }
    __shared__ int s_ticket;
    if (t == 0) {
        g_part[kb * NMT + mtb] = s_red[0];
        __threadfence();
        s_ticket = atomicAdd(&g_ctr, 1);
    }
    __syncthreads();

    // ---- last CTA: deterministic final commit reduction ----
    if (s_ticket == NCTAS - 1) {
        __threadfence();
        if (t < KB) {
            float s = 0.f;
            for (int i = 0; i < NMT; i++)         // fixed order: deterministic
                s += g_part[t * NMT + i];
            out[COMMIT_OFF + t] = s * (1.0f / (float)(ROWS * DIM));
        }
        if (t == 0) g_ctr = 0;                    // reset for next graph replay
    }
}

extern "C" void kernel_launch(void* const* d_in, const int* in_sizes, int n_in,
                              void* d_out, int out_size) {
    const float* x  = (const float*)d_in[0];   // [4,2048,512]
    const float* cb = (const float*)d_in[1];   // [8,1024,64]
    float* out = (float*)d_out;
    (void)in_sizes; (void)n_in; (void)out_size;

    cudaFuncSetAttribute(vq_mma_kernel,
                         cudaFuncAttributeMaxDynamicSharedMemorySize, SM_TOTAL);

    prep_cb_kernel<<<(KB * CB * 4) / 256, 256>>>(cb);
    vq_mma_kernel<<<dim3(NMT, KB), NTHR, SM_TOTAL>>>(x, cb, out);
}

// round 12
// speedup vs baseline: 1.0128x; 1.0128x over previous
#include <cuda_runtime.h>
#include <cuda_fp16.h>
#include <cstdint>

// ---------------- problem constants ----------------
#define KB      8
#define DIM     64
#define CB      1024
#define ROWS    8192
#define D_FULL  512
#define MT      128              // rows per CTA
#define NMT     (ROWS/MT)        // 64
#define NTHR    256
#define NCHUNK  8                // code chunks of 128
#define NCTAS   (NMT*KB)         // 512

#define CODES_ELEMS (ROWS*KB*DIM)            // 4194304
#define INDS_OFF    CODES_ELEMS
#define COMMIT_OFF  (CODES_ELEMS + ROWS*KB)  // 4259840

// ---------------- device scratch ----------------
__device__ float  g_esq[KB*CB];
__device__ float  g_part[KB*NMT];
__device__ __half g_Bh[(size_t)KB*CB*DIM];   // 1 MB
__device__ int    g_ctr;                     // zero-initialized; reset by last CTA

// ---------------- smem layout (bytes, dynamic) ----------------
#define SM_ESQ    0                 // 4096
#define SM_AH     4096              // 16384
#define SM_B      20480             // 3 stages x 16384 = 49152
#define SM_MB1    69632             // 2*128 floats
#define SM_MB2    70656             // 2*128 floats
#define SM_RED    71680             // 256 floats
#define SM_TOTAL  72704

#define SWZ(bo) ((bo) ^ (((bo) >> 3) & 0x70))

// ---------------- helpers ----------------
__device__ __forceinline__ uint32_t smem_u32(const void* p) {
    uint32_t a;
    asm("{ .reg .u64 t; cvta.to.shared.u64 t, %1; cvt.u32.u64 %0, t; }" : "=r"(a) : "l"(p));
    return a;
}
__device__ __forceinline__ void cp16(uint32_t saddr, const void* gptr) {
    asm volatile("cp.async.cg.shared.global [%0], [%1], 16;"
                 :: "r"(saddr), "l"(gptr) : "memory");
}
#define CP_COMMIT() asm volatile("cp.async.commit_group;" ::: "memory")
#define CP_WAIT(n)  asm volatile("cp.async.wait_group %0;" :: "n"(n) : "memory")

__device__ __forceinline__ void ldsm_x4(uint32_t& r0, uint32_t& r1,
                                        uint32_t& r2, uint32_t& r3, uint32_t addr) {
    asm volatile("ldmatrix.sync.aligned.m8n8.x4.shared.b16 {%0,%1,%2,%3}, [%4];"
                 : "=r"(r0), "=r"(r1), "=r"(r2), "=r"(r3) : "r"(addr));
}
__device__ __forceinline__ void mma16816(float* c, const uint32_t* a, const uint32_t* b) {
    asm volatile("mma.sync.aligned.m16n8k16.row.col.f32.f16.f16.f32 "
                 "{%0,%1,%2,%3}, {%4,%5,%6,%7}, {%8,%9}, {%0,%1,%2,%3};"
                 : "+f"(c[0]), "+f"(c[1]), "+f"(c[2]), "+f"(c[3])
                 : "r"(a[0]), "r"(a[1]), "r"(a[2]), "r"(a[3]), "r"(b[0]), "r"(b[1]));
}
__device__ __forceinline__ uint32_t pack_h2(float a, float b) {
    __half2 h = __floats2half2_rn(a, b);
    return *reinterpret_cast<uint32_t*>(&h);
}
// pack score with 10-bit code index in low mantissa bits (branchless argmin key)
__device__ __forceinline__ float pk(float v, int code) {
    return __uint_as_float((__float_as_uint(v) & 0xFFFFFC00u) | (uint32_t)code);
}
// branchless 2-smallest insert
__device__ __forceinline__ void min2(float& B1, float& B2, float v) {
    float lo = fminf(B1, v);
    float hi = fmaxf(B1, v);
    B1 = lo;
    B2 = fminf(B2, hi);
}
// merge two sorted pairs -> 2 smallest of 4 (branchless)
__device__ __forceinline__ void merge2(float& B1, float& B2, float o1, float o2) {
    float lo = fminf(B1, o1);
    float hi = fmaxf(B1, o1);
    B2 = fminf(fminf(B2, o2), hi);
    B1 = lo;
}

// ---------------- kernel: esq + codebook fp16 split (4 threads/code) ------------
__global__ void prep_cb_kernel(const float* __restrict__ cb) {
    int idx = blockIdx.x * blockDim.x + threadIdx.x;   // 0..32767
    int c = idx >> 2, h = idx & 3;
    const float4* p = reinterpret_cast<const float4*>(cb + (size_t)c * DIM + h * 16);
    uint2* ph = reinterpret_cast<uint2*>(g_Bh + (size_t)c * DIM + h * 16);
    float s = 0.f;
#pragma unroll
    for (int i = 0; i < 4; i++) {
        float4 v = p[i];
        s += v.x * v.x + v.y * v.y + v.z * v.z + v.w * v.w;
        uint2 uh;
        uh.x = pack_h2(v.x, v.y);
        uh.y = pack_h2(v.z, v.w);
        ph[i] = uh;
    }
    s += __shfl_xor_sync(0xffffffffu, s, 1);
    s += __shfl_xor_sync(0xffffffffu, s, 2);
    if (h == 0) g_esq[c] = s;
}

// ---------------- main kernel: fp16 MMA computes dist directly + packed argmin ---
// A = -2*x (fp16), acc initialized with esq  =>  acc = esq - 2*x.e = distance
__global__ __launch_bounds__(NTHR, 2)
void vq_mma_kernel(const float* __restrict__ x,
                   const float* __restrict__ cbook,
                   float* __restrict__ out) {
    extern __shared__ char smem[];
    const uint32_t sb = smem_u32(smem);
    float* esq_s = reinterpret_cast<float*>(smem + SM_ESQ);

    const int t = threadIdx.x, wid = t >> 5, l = t & 31;
    const int mtb = blockIdx.x, kb = blockIdx.y;
    const int warp_r = wid & 3;          // 4 row groups of 32 rows
    const int warp_c = wid >> 2;         // 2 code halves of 64 codes

    // ---- prefetch chunk 0 (B hi) via cp.async ----
    {
        const char* gh = reinterpret_cast<const char*>(g_Bh + (size_t)kb * CB * DIM);
#pragma unroll
        for (int i = 0; i < 4; i++) {
            int f = t + i * NTHR;
            uint32_t bo = SWZ((uint32_t)f * 16u);
            cp16(sb + SM_B + bo, gh + (size_t)f * 16);
        }
        CP_COMMIT();
    }

    // stage esq (exact fp32)
    for (int i = t; i < CB; i += NTHR) esq_s[i] = g_esq[kb * CB + i];

    // ---- stage A: (-2*x) tile as fp16, swizzled (x2 scaling exact in fp16) ----
    {
        const int r = t >> 1, h = t & 1;
        const float4* src = reinterpret_cast<const float4*>(
            x + (size_t)(mtb * MT + r) * D_FULL + kb * DIM + h * 32);
#pragma unroll
        for (int j = 0; j < 8; j++) {
            float4 v = src[j];
            uint2 uh;
            uh.x = pack_h2(-2.f * v.x, -2.f * v.y);
            uh.y = pack_h2(-2.f * v.z, -2.f * v.w);
            uint32_t bo = SWZ((uint32_t)(r * 128 + h * 64 + j * 8));
            *reinterpret_cast<uint2*>(smem + SM_AH + bo) = uh;
        }
    }

    float best1[4], best2[4];
#pragma unroll
    for (int s = 0; s < 4; s++) { best1[s] = 3.4e38f; best2[s] = 3.4e38f; }

    // stage index ring (mod 3)
    int cur = 0, nxt = 1;
#pragma unroll 1
    for (int ch = 0; ch < NCHUNK; ch++) {
        const uint32_t stg = sb + SM_B + (uint32_t)cur * 16384u;
        // issue prefetch of chunk ch+1 into the next ring stage, then wait for ch
        if (ch < NCHUNK - 1) {
            const uint32_t nstg = sb + SM_B + (uint32_t)nxt * 16384u;
            const char* gh = reinterpret_cast<const char*>(
                g_Bh + ((size_t)kb * CB + (ch + 1) * 128) * DIM);
#pragma unroll
            for (int i = 0; i < 4; i++) {
                int f = t + i * NTHR;
                uint32_t bo = SWZ((uint32_t)f * 16u);
                cp16(nstg + bo, gh + (size_t)f * 16);
            }
            CP_COMMIT();
            CP_WAIT(1);
        } else {
            CP_WAIT(0);
        }
        __syncthreads();   // single barrier/iter; 3 stages => write target never
                           // collides with a readable stage under <1-iter skew

#pragma unroll 1
        for (int nh = 0; nh < 2; nh++) {              // 2 halves of 32 codes
            const int cb0 = ch * 128 + warp_c * 64 + nh * 32 + 2 * (l & 3);

            // ---- init accumulators with esq => MMA output IS the distance ----
            float acc[2][4][4];
#pragma unroll
            for (int n = 0; n < 4; n++) {
                float e0 = esq_s[cb0 + n * 8];
                float e1 = esq_s[cb0 + n * 8 + 1];
#pragma unroll
                for (int m = 0; m < 2; m++) {
                    acc[m][n][0] = e0; acc[m][n][1] = e1;
                    acc[m][n][2] = e0; acc[m][n][3] = e1;
                }
            }

            // single pass: (-2*xh) * eh (residuals handled by exact top-2 rescore)
#pragma unroll
            for (int ks = 0; ks < 4; ks++) {
                uint32_t a[2][4];
#pragma unroll
                for (int m = 0; m < 2; m++) {
                    int row = warp_r * 32 + m * 16 + (l & 15);
                    uint32_t ad = sb + SM_AH +
                        SWZ((uint32_t)(row * 128 + ks * 32 + (l >> 4) * 16));
                    ldsm_x4(a[m][0], a[m][1], a[m][2], a[m][3], ad);
                }
                uint32_t b[4][2];
#pragma unroll
                for (int np = 0; np < 2; np++) {
                    int crow = warp_c * 64 + nh * 32 + np * 16 +
                               ((l >> 4) & 1) * 8 + (l & 7);
                    uint32_t bd = stg +
                        SWZ((uint32_t)(crow * 128 + ks * 32 + ((l >> 3) & 1) * 16));
                    uint32_t r0, r1, r2, r3;
                    ldsm_x4(r0, r1, r2, r3, bd);
                    b[np * 2][0] = r0;     b[np * 2][1] = r1;
                    b[np * 2 + 1][0] = r2; b[np * 2 + 1][1] = r3;
                }
#pragma unroll
                for (int m = 0; m < 2; m++)
#pragma unroll
                    for (int n = 0; n < 4; n++)
                        mma16816(acc[m][n], a[m], b[n]);
            }

            // ---- scoring: acc already = dist; pack index, branchless 2-min ----
#pragma unroll
            for (int m = 0; m < 2; m++)
#pragma unroll
                for (int n = 0; n < 4; n++) {
                    const int cbase = cb0 + n * 8;
                    const int s0 = 2 * m, s1 = 2 * m + 1;
                    min2(best1[s0], best2[s0], pk(acc[m][n][0], cbase));
                    min2(best1[s0], best2[s0], pk(acc[m][n][1], cbase + 1));
                    min2(best1[s1], best2[s1], pk(acc[m][n][2], cbase));
                    min2(best1[s1], best2[s1], pk(acc[m][n][3], cbase + 1));
                }
        }
        cur = nxt;
        nxt = (nxt == 2) ? 0 : nxt + 1;
    }

    // ---- reduce top-2 across the 4 lanes of each quad (l&3) ----
#pragma unroll
    for (int s = 0; s < 4; s++) {
#pragma unroll
        for (int m = 1; m <= 2; m <<= 1) {
            float o1 = __shfl_xor_sync(0xffffffffu, best1[s], m);
            float o2 = __shfl_xor_sync(0xffffffffu, best2[s], m);
            merge2(best1[s], best2[s], o1, o2);
        }
    }
    __syncthreads();
    float* mb1 = reinterpret_cast<float*>(smem + SM_MB1);
    float* mb2 = reinterpret_cast<float*>(smem + SM_MB2);
    if ((l & 3) == 0) {
#pragma unroll
        for (int s = 0; s < 4; s++) {
            int row = warp_r * 32 + (s >> 1) * 16 + (s & 1) * 8 + (l >> 2);
            mb1[warp_c * 128 + row] = best1[s];
            mb2[warp_c * 128 + row] = best2[s];
        }
    }
    __syncthreads();

    // ---- per-row epilogue (threads 0..127) ----
    float csum = 0.f;
    if (t < MT) {
        float B1 = mb1[t], B2 = mb2[t];
        merge2(B1, B2, mb1[128 + t], mb2[128 + t]);
        int I1 = (int)(__float_as_uint(B1) & 1023u);
        int I2 = (int)(__float_as_uint(B2) & 1023u);

        const int row_g = mtb * MT + t;
        const float4* xp = reinterpret_cast<const float4*>(
            x + (size_t)row_g * D_FULL + kb * DIM);
        float4 xr[16];
#pragma unroll
        for (int i = 0; i < 16; i++) xr[i] = xp[i];

        // near-tie safety: exact fp32 rescore of top-2
        // (fp16 approx err ~5.4e-3 + packing noise ~0.03 << 0.15 threshold)
        if (B2 - B1 < 0.15f) {
            const float* base = cbook + (size_t)kb * CB * DIM;
            float d1 = 0.f, d2 = 0.f;
            const float4* p1 = reinterpret_cast<const float4*>(base + (size_t)I1 * DIM);
            const float4* p2 = reinterpret_cast<const float4*>(base + (size_t)I2 * DIM);
#pragma unroll
            for (int i = 0; i < 16; i++) {
                float4 e1 = p1[i], e2 = p2[i];
                d1 = fmaf(xr[i].x, e1.x, d1); d1 = fmaf(xr[i].y, e1.y, d1);
                d1 = fmaf(xr[i].z, e1.z, d1); d1 = fmaf(xr[i].w, e1.w, d1);
                d2 = fmaf(xr[i].x, e2.x, d2); d2 = fmaf(xr[i].y, e2.y, d2);
                d2 = fmaf(xr[i].z, e2.z, d2); d2 = fmaf(xr[i].w, e2.w, d2);
            }
            float s1 = fmaf(-2.f, d1, esq_s[I1]);
            float s2 = fmaf(-2.f, d2, esq_s[I2]);
            if (s2 < s1 || (s2 == s1 && I2 < I1)) I1 = I2;
        }

        out[INDS_OFF + (size_t)row_g * KB + kb] = (float)I1;

        const float4* ep = reinterpret_cast<const float4*>(
            cbook + ((size_t)kb * CB + I1) * DIM);
        float4* op = reinterpret_cast<float4*>(
            out + (size_t)row_g * D_FULL + kb * DIM);
#pragma unroll
        for (int i = 0; i < 16; i++) {
            float4 e = ep[i];
            op[i] = e;
            float dx = xr[i].x - e.x, dy = xr[i].y - e.y;
            float dz = xr[i].z - e.z, dw = xr[i].w - e.w;
            csum += dx * dx + dy * dy + dz * dz + dw * dw;
        }
    }

    // deterministic commit-partial block reduce
    float* s_red = reinterpret_cast<float*>(smem + SM_RED);
    s_red[t] = csum;
    __syncthreads();
    for (int s = NTHR / 2; s > 0; s >>= 1) {
        if (t < s) s_red[t] += s_red[t + s];
        __syncthreads();
    }
    __shared__ int s_ticket;
    if (t == 0) {
        g_part[kb * NMT + mtb] = s_red[0];
        __threadfence();
        s_ticket = atomicAdd(&g_ctr, 1);
    }
    __syncthreads();

    // ---- last CTA: deterministic final commit reduction ----
    if (s_ticket == NCTAS - 1) {
        __threadfence();
        if (t < KB) {
            float s = 0.f;
            for (int i = 0; i < NMT; i++)         // fixed order: deterministic
                s += g_part[t * NMT + i];
            out[COMMIT_OFF + t] = s * (1.0f / (float)(ROWS * DIM));
        }
        if (t == 0) g_ctr = 0;                    // reset for next graph replay
    }
}

extern "C" void kernel_launch(void* const* d_in, const int* in_sizes, int n_in,
                              void* d_out, int out_size) {
    const float* x  = (const float*)d_in[0];   // [4,2048,512]
    const float* cb = (const float*)d_in[1];   // [8,1024,64]
    float* out = (float*)d_out;
    (void)in_sizes; (void)n_in; (void)out_size;

    cudaFuncSetAttribute(vq_mma_kernel,
                         cudaFuncAttributeMaxDynamicSharedMemorySize, SM_TOTAL);

    prep_cb_kernel<<<(KB * CB * 4) / 256, 256>>>(cb);
    vq_mma_kernel<<<dim3(NMT, KB), NTHR, SM_TOTAL>>>(x, cb, out);
}